// round 9
// baseline (speedup 1.0000x reference)
#include <cuda_runtime.h>
#include <cuda_fp16.h>
#include <cstdint>

#define N_NODES 40000
#define N_EDGES 640000
#define IN_F    128
#define HID     256
#define CLS     40
#define ROW4    (IN_F/4)
#define ROWH    32
#define NBLK    157

typedef unsigned long long ull;

// packed f32x2 helpers
#define FMA2(d, a, b)    asm("fma.rn.f32x2 %0, %1, %2, %3;" : "=l"(d) : "l"(a), "l"(b), "l"(d))
#define UNPACK2(lo, hi, s) asm("mov.b64 {%0, %1}, %2;" : "=f"(lo), "=f"(hi) : "l"(s))

__device__ __forceinline__ uint2 pack4h(float4 a) {
    __half2 lo = __floats2half2_rn(a.x, a.y);
    __half2 hi = __floats2half2_rn(a.z, a.w);
    uint2 r;
    r.x = *reinterpret_cast<unsigned*>(&lo);
    r.y = *reinterpret_cast<unsigned*>(&hi);
    return r;
}
__device__ __forceinline__ float4 unpack4h(uint2 v) {
    __half2 lo = *reinterpret_cast<__half2*>(&v.x);
    __half2 hi = *reinterpret_cast<__half2*>(&v.y);
    float2 a = __half22float2(lo);
    float2 b = __half22float2(hi);
    return make_float4(a.x, a.y, b.x, b.y);
}

// ---- scratch ----
__device__ int    g_deg[N_NODES];
__device__ int    g_rowptr[N_NODES + 1];
__device__ int    g_cursor[N_NODES];
__device__ int    g_part[NBLK];             // lookback partials (init -1)
__device__ int    g_csr[N_EDGES];
__device__ float  g_norm[N_NODES];
__device__ uint2  g_featH[N_NODES * ROWH];  // feat*norm, fp16 (gather1 input)
__device__ uint2  g_bufH[N_NODES * ROWH];   // hop1 out, fp16 (MLP gather input)
__device__ __half g_W1h[HID * IN_F];        // W1^T fp16: [n][k]

// ================= preamble =================
// degree, 4 edges/thread
__global__ __launch_bounds__(256)
void k_deg4(const int4* __restrict__ dst4) {
    int e = blockIdx.x * blockDim.x + threadIdx.x;   // < 160000
    int4 d = dst4[e];
    atomicAdd(&g_deg[d.x], 1);
    atomicAdd(&g_deg[d.y], 1);
    atomicAdd(&g_deg[d.z], 1);
    atomicAdd(&g_deg[d.w], 1);
}

// single-kernel exclusive scan via decoupled lookback (+cursor +norm)
__global__ __launch_bounds__(256)
void k_scan() {
    __shared__ int sm[256];
    const int t = threadIdx.x;
    const int b = blockIdx.x;
    const int i = b * 256 + t;
    int v = (i < N_NODES) ? g_deg[i] : 0;

    // block-local inclusive scan
    sm[t] = v;
    __syncthreads();
    int acc = v;
    for (int o = 1; o < 256; o <<= 1) {
        int u = (t >= o) ? sm[t - o] : 0;
        __syncthreads();
        acc += u;
        sm[t] = acc;
        __syncthreads();
    }
    int S = sm[255];                          // block total

    // publish our partial (g_part pre-set to -1 by memset)
    if (t == 0) atomicExch(&g_part[b], S);

    // gather predecessor partials (thread t waits on block t, t < b)
    int part = 0;
    if (t < b) {
        int p;
        do { p = atomicAdd(&g_part[t], 0); } while (p < 0);
        part = p;
    }
    __syncthreads();                          // sm dead, reuse for reduction
    sm[t] = part;
    __syncthreads();
    for (int o = 128; o > 0; o >>= 1) {
        if (t < o) sm[t] += sm[t + o];
        __syncthreads();
    }
    int off = sm[0];

    if (i < N_NODES) {
        int rp = acc - v + off;               // exclusive prefix
        g_rowptr[i] = rp;
        g_cursor[i] = rp;
        g_norm[i] = rsqrtf(fmaxf((float)v, 1.0f));
    }
    if (b == NBLK - 1 && t == 0) g_rowptr[N_NODES] = off + S;
}

__global__ __launch_bounds__(256)
void k_prescale(const float4* __restrict__ feat4) {
    int t = blockIdx.x * blockDim.x + threadIdx.x;
    float n = g_norm[t >> 5];
    float4 v = feat4[t];
    v.x *= n; v.y *= n; v.z *= n; v.w *= n;
    g_featH[t] = pack4h(v);
}

// W1^T fp16 prep: g_W1h[n*128+k] = fp16(W1[k][n])
__global__ __launch_bounds__(256)
void k_prepW(const float* __restrict__ W1) {
    int i = blockIdx.x * 256 + threadIdx.x;
    int k = i >> 8, n = i & 255;
    g_W1h[n * IN_F + k] = __float2half(W1[i]);
}

// CSR fill, 4 edges/thread
__global__ __launch_bounds__(256)
void k_fill4(const int4* __restrict__ src4, const int4* __restrict__ dst4) {
    int e = blockIdx.x * blockDim.x + threadIdx.x;
    int4 s = src4[e];
    int4 d = dst4[e];
    g_csr[atomicAdd(&g_cursor[d.x], 1)] = s.x;
    g_csr[atomicAdd(&g_cursor[d.y], 1)] = s.y;
    g_csr[atomicAdd(&g_cursor[d.z], 1)] = s.z;
    g_csr[atomicAdd(&g_cursor[d.w], 1)] = s.w;
}

__global__ __launch_bounds__(256)
void k_sort() {
    __shared__ int scratch[8][512];
    const int wi   = threadIdx.x >> 5;
    const int lane = threadIdx.x & 31;
    const int n = blockIdx.x * 8 + wi;
    int b = g_rowptr[n], e = g_rowptr[n + 1];
    int d = e - b;
    if (d <= 1) return;
    if (d <= 32) {
        int v = (lane < d) ? g_csr[b + lane] : 0x7fffffff;
        #pragma unroll
        for (int k = 2; k <= 32; k <<= 1) {
            #pragma unroll
            for (int j = k >> 1; j > 0; j >>= 1) {
                int pv = __shfl_xor_sync(0xffffffffu, v, j);
                bool dir   = ((lane & k) == 0);
                bool lower = ((lane & j) == 0);
                v = ((lower == dir) ? min(v, pv) : max(v, pv));
            }
        }
        if (lane < d) g_csr[b + lane] = v;
    } else if (d <= 512) {
        int* s = scratch[wi];
        for (int i = lane; i < d; i += 32) s[i] = g_csr[b + i];
        __syncwarp();
        if (lane == 0) {
            for (int i = 1; i < d; i++) {
                int v = s[i], j = i - 1;
                while (j >= 0 && s[j] > v) { s[j + 1] = s[j]; j--; }
                s[j + 1] = v;
            }
        }
        __syncwarp();
        for (int i = lane; i < d; i += 32) g_csr[b + i] = s[i];
    } else {
        if (lane == 0) {
            for (int i = b + 1; i < e; i++) {
                int v = g_csr[i], j = i - 1;
                while (j >= b && g_csr[j] > v) { g_csr[j + 1] = g_csr[j]; j--; }
                g_csr[j + 1] = v;
            }
        }
    }
}

// ================= hop 1 gather =================
__global__ __launch_bounds__(256)
void k_gather1() {
    int gt = blockIdx.x * blockDim.x + threadIdx.x;
    int w = gt >> 5, lane = gt & 31;
    int beg = g_rowptr[w], end = g_rowptr[w + 1];
    float4 acc = make_float4(0.f, 0.f, 0.f, 0.f);
    for (int base = beg; base < end; base += 32) {
        int cnt = min(32, end - base);
        int idx = base + lane;
        int s_l = (idx < end) ? g_csr[idx] : 0;
        int k = 0;
        for (; k + 8 <= cnt; k += 8) {
            int s[8];
            #pragma unroll
            for (int i = 0; i < 8; i++) s[i] = __shfl_sync(0xffffffffu, s_l, k + i);
            uint2 h[8];
            #pragma unroll
            for (int i = 0; i < 8; i++) h[i] = g_featH[s[i] * ROWH + lane];
            #pragma unroll
            for (int i = 0; i < 8; i++) {
                float4 v = unpack4h(h[i]);
                acc.x += v.x; acc.y += v.y; acc.z += v.z; acc.w += v.w;
            }
        }
        for (; k < cnt; k++) {
            int s = __shfl_sync(0xffffffffu, s_l, k);
            float4 v = unpack4h(g_featH[s * ROWH + lane]);
            acc.x += v.x; acc.y += v.y; acc.z += v.z; acc.w += v.w;
        }
    }
    float nn = g_norm[w];
    float sc = nn * nn;
    acc.x *= sc; acc.y *= sc; acc.z *= sc; acc.w *= sc;
    g_bufH[w * ROWH + lane] = pack4h(acc);
}

// ================= fused hop2 + MLP (HMMA) =================
// CTA = 64 rows, 256 threads (8 warps).
// Phase 0: warp w gathers rows w*8..+7 from g_bufH -> fp16 smHA.
// Phase 1: GEMM1 mma.sync m16n8k16 (warp w: rows (w&3)*16..+15, cols (w>>2)*128..+127).
// Phase 2: GEMM2 SIMT FMA2 + shuffle reduce.
#define HPAD 68
#define ZSTR 264
#define MLP_SMEM 129024
__global__ __launch_bounds__(256)
void k_mlp(const float* __restrict__ b1, const float* __restrict__ W2,
           const float* __restrict__ b2, float* __restrict__ out) {
    extern __shared__ __align__(16) char dyn[];
    unsigned* smHA  = reinterpret_cast<unsigned*>(dyn);                // fp16 [64][136]
    unsigned* smW1  = reinterpret_cast<unsigned*>(dyn + 17408);        // fp16 [256][136]
    float*    smZ   = reinterpret_cast<float*>(dyn + 17408);           // fp32 [64][264]
    float*    smW2  = reinterpret_cast<float*>(dyn + 87040);           // fp32 [40][256]
    float*    smB1  = reinterpret_cast<float*>(dyn + 128000);          // fp32 [256]

    const int t    = threadIdx.x;
    const int wid  = t >> 5;
    const int lane = t & 31;
    const int row0 = blockIdx.x * 64;

    // ---- load W1T (fp16): 4096 uint4 ----
    {
        const uint4* srcW = reinterpret_cast<const uint4*>(g_W1h);
        uint4* dstW = reinterpret_cast<uint4*>(smW1);
        #pragma unroll
        for (int it = 0; it < 16; it++) {
            int idx = it * 256 + t;
            int r = idx >> 4, q = idx & 15;
            dstW[r * 17 + q] = srcW[idx];
        }
    }
    smB1[t] = b1[t];

    // ---- phase 0: gather hop 2 into smHA (warp wid -> rows wid*8..+7) ----
    #pragma unroll 1
    for (int rr = 0; rr < 8; rr++) {
        const int w = row0 + wid * 8 + rr;
        int beg = g_rowptr[w], end = g_rowptr[w + 1];
        float4 acc = make_float4(0.f, 0.f, 0.f, 0.f);
        for (int base = beg; base < end; base += 32) {
            int cnt = min(32, end - base);
            int idx = base + lane;
            int s_l = (idx < end) ? g_csr[idx] : 0;
            int k = 0;
            for (; k + 8 <= cnt; k += 8) {
                int s[8];
                #pragma unroll
                for (int i = 0; i < 8; i++) s[i] = __shfl_sync(0xffffffffu, s_l, k + i);
                uint2 h[8];
                #pragma unroll
                for (int i = 0; i < 8; i++) h[i] = g_bufH[s[i] * ROWH + lane];
                #pragma unroll
                for (int i = 0; i < 8; i++) {
                    float4 v = unpack4h(h[i]);
                    acc.x += v.x; acc.y += v.y; acc.z += v.z; acc.w += v.w;
                }
            }
            for (; k < cnt; k++) {
                int s = __shfl_sync(0xffffffffu, s_l, k);
                float4 v = unpack4h(g_bufH[s * ROWH + lane]);
                acc.x += v.x; acc.y += v.y; acc.z += v.z; acc.w += v.w;
            }
        }
        float nn = g_norm[w];
        acc.x *= nn; acc.y *= nn; acc.z *= nn; acc.w *= nn;
        uint2 p = pack4h(acc);
        smHA[(wid * 8 + rr) * HPAD + lane * 2]     = p.x;
        smHA[(wid * 8 + rr) * HPAD + lane * 2 + 1] = p.y;
    }
    __syncthreads();

    // ---- phase 1: GEMM1, 8 k-steps x 16 n8-tiles ----
    const int mrow0 = (wid & 3) * 16;
    const int ncol0 = (wid >> 2) * 128;
    const int g  = lane >> 2;
    const int ct = lane & 3;

    float acc[16][4];
    #pragma unroll
    for (int nt = 0; nt < 16; nt++)
        #pragma unroll
        for (int q = 0; q < 4; q++) acc[nt][q] = 0.f;

    #pragma unroll
    for (int kt = 0; kt < 8; kt++) {
        const int kw = kt * 8 + ct;
        unsigned a0 = smHA[(mrow0 + g) * HPAD + kw];
        unsigned a1 = smHA[(mrow0 + g + 8) * HPAD + kw];
        unsigned a2 = smHA[(mrow0 + g) * HPAD + kw + 4];
        unsigned a3 = smHA[(mrow0 + g + 8) * HPAD + kw + 4];
        #pragma unroll
        for (int nt = 0; nt < 16; nt++) {
            const int n = ncol0 + nt * 8 + g;
            unsigned b0 = smW1[n * HPAD + kw];
            unsigned b1r = smW1[n * HPAD + kw + 4];
            asm volatile(
                "mma.sync.aligned.m16n8k16.row.col.f32.f16.f16.f32 "
                "{%0,%1,%2,%3}, {%4,%5,%6,%7}, {%8,%9}, {%0,%1,%2,%3};"
                : "+f"(acc[nt][0]), "+f"(acc[nt][1]), "+f"(acc[nt][2]), "+f"(acc[nt][3])
                : "r"(a0), "r"(a1), "r"(a2), "r"(a3), "r"(b0), "r"(b1r));
        }
    }

    // ---- W2^T load overlaps MMA tail ----
    for (int i = t; i < CLS * HID; i += 256) {
        int c = i >> 8, k = i & 255;
        smW2[c * HID + k] = W2[k * CLS + c];
    }

    // ---- bias + relu + z to smem (W1T region dead) ----
    __syncthreads();
    #pragma unroll
    for (int nt = 0; nt < 16; nt++) {
        const int col = ncol0 + nt * 8 + ct * 2;
        float bi0 = smB1[col], bi1 = smB1[col + 1];
        float2 z0, z1;
        z0.x = fmaxf(acc[nt][0] + bi0, 0.f);
        z0.y = fmaxf(acc[nt][1] + bi1, 0.f);
        z1.x = fmaxf(acc[nt][2] + bi0, 0.f);
        z1.y = fmaxf(acc[nt][3] + bi1, 0.f);
        *reinterpret_cast<float2*>(smZ + (mrow0 + g) * ZSTR + col)     = z0;
        *reinterpret_cast<float2*>(smZ + (mrow0 + g + 8) * ZSTR + col) = z1;
    }
    __syncthreads();

    // ---- phase 2: GEMM2 (warp wid -> rows wid*8..+7) ----
    const int rbase = wid * 8;
    ull zp[8][4];
    #pragma unroll
    for (int rr = 0; rr < 8; rr++) {
        const ulonglong2* zr =
            reinterpret_cast<const ulonglong2*>(smZ + (rbase + rr) * ZSTR + lane * 8);
        ulonglong2 a = zr[0], b = zr[1];
        zp[rr][0] = a.x; zp[rr][1] = a.y; zp[rr][2] = b.x; zp[rr][3] = b.y;
    }
    #pragma unroll 1
    for (int c = 0; c < CLS; c++) {
        const ulonglong2* wp =
            reinterpret_cast<const ulonglong2*>(smW2 + c * HID + lane * 8);
        ulonglong2 wA = wp[0], wB = wp[1];
        float p[8];
        #pragma unroll
        for (int rr = 0; rr < 8; rr++) {
            ull s2 = 0ull;
            FMA2(s2, zp[rr][0], wA.x);
            FMA2(s2, zp[rr][1], wA.y);
            FMA2(s2, zp[rr][2], wB.x);
            FMA2(s2, zp[rr][3], wB.y);
            float lo, hi;
            UNPACK2(lo, hi, s2);
            p[rr] = lo + hi;
        }
        #pragma unroll
        for (int off = 16; off > 0; off >>= 1) {
            #pragma unroll
            for (int rr = 0; rr < 8; rr++)
                p[rr] += __shfl_xor_sync(0xffffffffu, p[rr], off);
        }
        if (lane == 0) {
            float bc = b2[c];
            #pragma unroll
            for (int rr = 0; rr < 8; rr++)
                out[(row0 + rbase + rr) * CLS + c] = p[rr] + bc;
        }
    }
}

// ================= launch =================
extern "C" void kernel_launch(void* const* d_in, const int* in_sizes, int n_in,
                              void* d_out, int out_size) {
    const float* features = (const float*)d_in[0];
    const int*   src      = (const int*)d_in[1];
    const int*   dst      = (const int*)d_in[2];
    const float* W1       = (const float*)d_in[3];
    const float* b1       = (const float*)d_in[4];
    const float* W2       = (const float*)d_in[5];
    const float* b2       = (const float*)d_in[6];
    float* out = (float*)d_out;

    const int edge4Blocks = N_EDGES / 4 / 256;      // 625
    const int warpBlocks  = N_NODES * 32 / 256;     // 5000
    const int sortBlocks  = N_NODES / 8;            // 5000
    const int mlpBlocks   = N_NODES / 64;           // 625

    static int init_done = 0;
    if (!init_done) {
        cudaFuncSetAttribute(k_mlp, cudaFuncAttributeMaxDynamicSharedMemorySize,
                             MLP_SMEM);
        init_done = 1;
    }

    void* degPtr = nullptr;
    void* partPtr = nullptr;
    cudaGetSymbolAddress(&degPtr, g_deg);
    cudaGetSymbolAddress(&partPtr, g_part);
    cudaMemsetAsync(degPtr, 0, N_NODES * sizeof(int));
    cudaMemsetAsync(partPtr, 0xFF, NBLK * sizeof(int));   // -1 sentinels

    k_prepW<<<128, 256>>>(W1);
    k_deg4<<<edge4Blocks, 256>>>((const int4*)dst);
    k_scan<<<NBLK, 256>>>();
    k_prescale<<<warpBlocks, 256>>>((const float4*)features);
    k_fill4<<<edge4Blocks, 256>>>((const int4*)src, (const int4*)dst);
    k_sort<<<sortBlocks, 256>>>();

    k_gather1<<<warpBlocks, 256>>>();
    k_mlp<<<mlpBlocks, 256, MLP_SMEM>>>(b1, W2, b2, out);
}

// round 10
// speedup vs baseline: 1.2362x; 1.2362x over previous
#include <cuda_runtime.h>
#include <cuda_fp16.h>
#include <cstdint>

#define N_NODES 40000
#define N_EDGES 640000
#define IN_F    128
#define HID     256
#define CLS     40
#define ROW4    (IN_F/4)
#define ROWH    32
#define NBLK    157

typedef unsigned long long ull;

// packed f32x2 helpers
#define FMA2(d, a, b)    asm("fma.rn.f32x2 %0, %1, %2, %3;" : "=l"(d) : "l"(a), "l"(b), "l"(d))
#define UNPACK2(lo, hi, s) asm("mov.b64 {%0, %1}, %2;" : "=f"(lo), "=f"(hi) : "l"(s))

__device__ __forceinline__ uint2 pack4h(float4 a) {
    __half2 lo = __floats2half2_rn(a.x, a.y);
    __half2 hi = __floats2half2_rn(a.z, a.w);
    uint2 r;
    r.x = *reinterpret_cast<unsigned*>(&lo);
    r.y = *reinterpret_cast<unsigned*>(&hi);
    return r;
}
__device__ __forceinline__ float4 unpack4h(uint2 v) {
    __half2 lo = *reinterpret_cast<__half2*>(&v.x);
    __half2 hi = *reinterpret_cast<__half2*>(&v.y);
    float2 a = __half22float2(lo);
    float2 b = __half22float2(hi);
    return make_float4(a.x, a.y, b.x, b.y);
}

// ---- scratch ----
__device__ int    g_deg[N_NODES];
__device__ int    g_rowptr[N_NODES + 1];
__device__ int    g_cursor[N_NODES];
__device__ int    g_part[NBLK];             // lookback partials (init -1)
__device__ int    g_csr[N_EDGES];
__device__ float  g_norm[N_NODES];
__device__ uint2  g_featH[N_NODES * ROWH];  // feat*norm fp16; REUSED as hop2 out
__device__ uint2  g_bufH[N_NODES * ROWH];   // hop1 out, fp16
__device__ __half g_W1h[HID * IN_F];        // W1^T fp16: [n][k]

// ================= preamble =================
__global__ __launch_bounds__(256)
void k_deg4(const int4* __restrict__ dst4) {
    int e = blockIdx.x * blockDim.x + threadIdx.x;
    int4 d = dst4[e];
    atomicAdd(&g_deg[d.x], 1);
    atomicAdd(&g_deg[d.y], 1);
    atomicAdd(&g_deg[d.z], 1);
    atomicAdd(&g_deg[d.w], 1);
}

// single-kernel exclusive scan via decoupled lookback (+cursor +norm)
__global__ __launch_bounds__(256)
void k_scan() {
    __shared__ int sm[256];
    const int t = threadIdx.x;
    const int b = blockIdx.x;
    const int i = b * 256 + t;
    int v = (i < N_NODES) ? g_deg[i] : 0;

    sm[t] = v;
    __syncthreads();
    int acc = v;
    for (int o = 1; o < 256; o <<= 1) {
        int u = (t >= o) ? sm[t - o] : 0;
        __syncthreads();
        acc += u;
        sm[t] = acc;
        __syncthreads();
    }
    int S = sm[255];

    if (t == 0) atomicExch(&g_part[b], S);

    int part = 0;
    if (t < b) {
        int p;
        do { p = atomicAdd(&g_part[t], 0); } while (p < 0);
        part = p;
    }
    __syncthreads();
    sm[t] = part;
    __syncthreads();
    for (int o = 128; o > 0; o >>= 1) {
        if (t < o) sm[t] += sm[t + o];
        __syncthreads();
    }
    int off = sm[0];

    if (i < N_NODES) {
        int rp = acc - v + off;
        g_rowptr[i] = rp;
        g_cursor[i] = rp;
        g_norm[i] = rsqrtf(fmaxf((float)v, 1.0f));
    }
    if (b == NBLK - 1 && t == 0) g_rowptr[N_NODES] = off + S;
}

__global__ __launch_bounds__(256)
void k_prescale(const float4* __restrict__ feat4) {
    int t = blockIdx.x * blockDim.x + threadIdx.x;
    float n = g_norm[t >> 5];
    float4 v = feat4[t];
    v.x *= n; v.y *= n; v.z *= n; v.w *= n;
    g_featH[t] = pack4h(v);
}

__global__ __launch_bounds__(256)
void k_prepW(const float* __restrict__ W1) {
    int i = blockIdx.x * 256 + threadIdx.x;
    int k = i >> 8, n = i & 255;
    g_W1h[n * IN_F + k] = __float2half(W1[i]);
}

__global__ __launch_bounds__(256)
void k_fill4(const int4* __restrict__ src4, const int4* __restrict__ dst4) {
    int e = blockIdx.x * blockDim.x + threadIdx.x;
    int4 s = src4[e];
    int4 d = dst4[e];
    g_csr[atomicAdd(&g_cursor[d.x], 1)] = s.x;
    g_csr[atomicAdd(&g_cursor[d.y], 1)] = s.y;
    g_csr[atomicAdd(&g_cursor[d.z], 1)] = s.z;
    g_csr[atomicAdd(&g_cursor[d.w], 1)] = s.w;
}

__global__ __launch_bounds__(256)
void k_sort() {
    __shared__ int scratch[8][512];
    const int wi   = threadIdx.x >> 5;
    const int lane = threadIdx.x & 31;
    const int n = blockIdx.x * 8 + wi;
    int b = g_rowptr[n], e = g_rowptr[n + 1];
    int d = e - b;
    if (d <= 1) return;
    if (d <= 32) {
        int v = (lane < d) ? g_csr[b + lane] : 0x7fffffff;
        #pragma unroll
        for (int k = 2; k <= 32; k <<= 1) {
            #pragma unroll
            for (int j = k >> 1; j > 0; j >>= 1) {
                int pv = __shfl_xor_sync(0xffffffffu, v, j);
                bool dir   = ((lane & k) == 0);
                bool lower = ((lane & j) == 0);
                v = ((lower == dir) ? min(v, pv) : max(v, pv));
            }
        }
        if (lane < d) g_csr[b + lane] = v;
    } else if (d <= 512) {
        int* s = scratch[wi];
        for (int i = lane; i < d; i += 32) s[i] = g_csr[b + i];
        __syncwarp();
        if (lane == 0) {
            for (int i = 1; i < d; i++) {
                int v = s[i], j = i - 1;
                while (j >= 0 && s[j] > v) { s[j + 1] = s[j]; j--; }
                s[j + 1] = v;
            }
        }
        __syncwarp();
        for (int i = lane; i < d; i += 32) g_csr[b + i] = s[i];
    } else {
        if (lane == 0) {
            for (int i = b + 1; i < e; i++) {
                int v = g_csr[i], j = i - 1;
                while (j >= b && g_csr[j] > v) { g_csr[j + 1] = g_csr[j]; j--; }
                g_csr[j + 1] = v;
            }
        }
    }
}

// ================= gathers (full occupancy, standalone) =================
__global__ __launch_bounds__(256)
void k_gather1() {
    int gt = blockIdx.x * blockDim.x + threadIdx.x;
    int w = gt >> 5, lane = gt & 31;
    int beg = g_rowptr[w], end = g_rowptr[w + 1];
    float4 acc = make_float4(0.f, 0.f, 0.f, 0.f);
    for (int base = beg; base < end; base += 32) {
        int cnt = min(32, end - base);
        int idx = base + lane;
        int s_l = (idx < end) ? g_csr[idx] : 0;
        int k = 0;
        for (; k + 8 <= cnt; k += 8) {
            int s[8];
            #pragma unroll
            for (int i = 0; i < 8; i++) s[i] = __shfl_sync(0xffffffffu, s_l, k + i);
            uint2 h[8];
            #pragma unroll
            for (int i = 0; i < 8; i++) h[i] = g_featH[s[i] * ROWH + lane];
            #pragma unroll
            for (int i = 0; i < 8; i++) {
                float4 v = unpack4h(h[i]);
                acc.x += v.x; acc.y += v.y; acc.z += v.z; acc.w += v.w;
            }
        }
        for (; k < cnt; k++) {
            int s = __shfl_sync(0xffffffffu, s_l, k);
            float4 v = unpack4h(g_featH[s * ROWH + lane]);
            acc.x += v.x; acc.y += v.y; acc.z += v.z; acc.w += v.w;
        }
    }
    float nn = g_norm[w];
    float sc = nn * nn;
    acc.x *= sc; acc.y *= sc; acc.z *= sc; acc.w *= sc;
    g_bufH[w * ROWH + lane] = pack4h(acc);
}

// hop2: reads g_bufH, writes fp16 h into g_featH (dead after gather1)
__global__ __launch_bounds__(256)
void k_gather2() {
    int gt = blockIdx.x * blockDim.x + threadIdx.x;
    int w = gt >> 5, lane = gt & 31;
    int beg = g_rowptr[w], end = g_rowptr[w + 1];
    float4 acc = make_float4(0.f, 0.f, 0.f, 0.f);
    for (int base = beg; base < end; base += 32) {
        int cnt = min(32, end - base);
        int idx = base + lane;
        int s_l = (idx < end) ? g_csr[idx] : 0;
        int k = 0;
        for (; k + 8 <= cnt; k += 8) {
            int s[8];
            #pragma unroll
            for (int i = 0; i < 8; i++) s[i] = __shfl_sync(0xffffffffu, s_l, k + i);
            uint2 h[8];
            #pragma unroll
            for (int i = 0; i < 8; i++) h[i] = g_bufH[s[i] * ROWH + lane];
            #pragma unroll
            for (int i = 0; i < 8; i++) {
                float4 v = unpack4h(h[i]);
                acc.x += v.x; acc.y += v.y; acc.z += v.z; acc.w += v.w;
            }
        }
        for (; k < cnt; k++) {
            int s = __shfl_sync(0xffffffffu, s_l, k);
            float4 v = unpack4h(g_bufH[s * ROWH + lane]);
            acc.x += v.x; acc.y += v.y; acc.z += v.z; acc.w += v.w;
        }
    }
    float nn = g_norm[w];
    acc.x *= nn; acc.y *= nn; acc.z *= nn; acc.w *= nn;
    g_featH[w * ROWH + lane] = pack4h(acc);
}

// ================= MLP via mma.sync (HMMA) =================
// CTA = 64 rows, 256 threads (8 warps). Warp w: rows (w&3)*16..+15, cols (w>>2)*128..+127.
#define HPAD 68
#define ZSTR 264
#define MLP_SMEM 129024
__global__ __launch_bounds__(256)
void k_mlp(const float* __restrict__ b1, const float* __restrict__ W2,
           const float* __restrict__ b2, float* __restrict__ out) {
    extern __shared__ __align__(16) char dyn[];
    unsigned* smHA  = reinterpret_cast<unsigned*>(dyn);                // fp16 [64][136]
    unsigned* smW1  = reinterpret_cast<unsigned*>(dyn + 17408);        // fp16 [256][136]
    float*    smZ   = reinterpret_cast<float*>(dyn + 17408);           // fp32 [64][264]
    float*    smW2  = reinterpret_cast<float*>(dyn + 87040);           // fp32 [40][256]
    float*    smB1  = reinterpret_cast<float*>(dyn + 128000);          // fp32 [256]

    const int t    = threadIdx.x;
    const int wid  = t >> 5;
    const int lane = t & 31;
    const int row0 = blockIdx.x * 64;

    // ---- load h tile (fp16, hop2 out): 4096 uints ----
    const unsigned* srcH = reinterpret_cast<const unsigned*>(g_featH) + row0 * 64;
    #pragma unroll
    for (int it = 0; it < 16; it++) {
        int idx = it * 256 + t;
        int r = idx >> 6, c = idx & 63;
        smHA[r * HPAD + c] = srcH[idx];
    }
    // ---- load W1T (fp16): 4096 uint4 ----
    {
        const uint4* srcW = reinterpret_cast<const uint4*>(g_W1h);
        uint4* dstW = reinterpret_cast<uint4*>(smW1);
        #pragma unroll
        for (int it = 0; it < 16; it++) {
            int idx = it * 256 + t;
            int r = idx >> 4, q = idx & 15;
            dstW[r * 17 + q] = srcW[idx];
        }
    }
    smB1[t] = b1[t];
    __syncthreads();

    // ---- GEMM1: 8 k-steps x 16 n8-tiles of m16n8k16 ----
    const int mrow0 = (wid & 3) * 16;
    const int ncol0 = (wid >> 2) * 128;
    const int g  = lane >> 2;
    const int ct = lane & 3;

    float acc[16][4];
    #pragma unroll
    for (int nt = 0; nt < 16; nt++)
        #pragma unroll
        for (int q = 0; q < 4; q++) acc[nt][q] = 0.f;

    #pragma unroll
    for (int kt = 0; kt < 8; kt++) {
        const int kw = kt * 8 + ct;
        unsigned a0 = smHA[(mrow0 + g) * HPAD + kw];
        unsigned a1 = smHA[(mrow0 + g + 8) * HPAD + kw];
        unsigned a2 = smHA[(mrow0 + g) * HPAD + kw + 4];
        unsigned a3 = smHA[(mrow0 + g + 8) * HPAD + kw + 4];
        #pragma unroll
        for (int nt = 0; nt < 16; nt++) {
            const int n = ncol0 + nt * 8 + g;
            unsigned b0 = smW1[n * HPAD + kw];
            unsigned b1r = smW1[n * HPAD + kw + 4];
            asm volatile(
                "mma.sync.aligned.m16n8k16.row.col.f32.f16.f16.f32 "
                "{%0,%1,%2,%3}, {%4,%5,%6,%7}, {%8,%9}, {%0,%1,%2,%3};"
                : "+f"(acc[nt][0]), "+f"(acc[nt][1]), "+f"(acc[nt][2]), "+f"(acc[nt][3])
                : "r"(a0), "r"(a1), "r"(a2), "r"(a3), "r"(b0), "r"(b1r));
        }
    }

    // ---- W2^T load overlaps MMA tail ----
    for (int i = t; i < CLS * HID; i += 256) {
        int c = i >> 8, k = i & 255;
        smW2[c * HID + k] = W2[k * CLS + c];
    }

    // ---- bias + relu + z to smem (W1T region dead) ----
    __syncthreads();
    #pragma unroll
    for (int nt = 0; nt < 16; nt++) {
        const int col = ncol0 + nt * 8 + ct * 2;
        float bi0 = smB1[col], bi1 = smB1[col + 1];
        float2 z0, z1;
        z0.x = fmaxf(acc[nt][0] + bi0, 0.f);
        z0.y = fmaxf(acc[nt][1] + bi1, 0.f);
        z1.x = fmaxf(acc[nt][2] + bi0, 0.f);
        z1.y = fmaxf(acc[nt][3] + bi1, 0.f);
        *reinterpret_cast<float2*>(smZ + (mrow0 + g) * ZSTR + col)     = z0;
        *reinterpret_cast<float2*>(smZ + (mrow0 + g + 8) * ZSTR + col) = z1;
    }
    __syncthreads();

    // ---- GEMM2: out = z @ W2 + b2 (warp wid -> rows wid*8..+7) ----
    const int rbase = wid * 8;
    ull zp[8][4];
    #pragma unroll
    for (int rr = 0; rr < 8; rr++) {
        const ulonglong2* zr =
            reinterpret_cast<const ulonglong2*>(smZ + (rbase + rr) * ZSTR + lane * 8);
        ulonglong2 a = zr[0], b = zr[1];
        zp[rr][0] = a.x; zp[rr][1] = a.y; zp[rr][2] = b.x; zp[rr][3] = b.y;
    }
    #pragma unroll 1
    for (int c = 0; c < CLS; c++) {
        const ulonglong2* wp =
            reinterpret_cast<const ulonglong2*>(smW2 + c * HID + lane * 8);
        ulonglong2 wA = wp[0], wB = wp[1];
        float p[8];
        #pragma unroll
        for (int rr = 0; rr < 8; rr++) {
            ull s2 = 0ull;
            FMA2(s2, zp[rr][0], wA.x);
            FMA2(s2, zp[rr][1], wA.y);
            FMA2(s2, zp[rr][2], wB.x);
            FMA2(s2, zp[rr][3], wB.y);
            float lo, hi;
            UNPACK2(lo, hi, s2);
            p[rr] = lo + hi;
        }
        #pragma unroll
        for (int off = 16; off > 0; off >>= 1) {
            #pragma unroll
            for (int rr = 0; rr < 8; rr++)
                p[rr] += __shfl_xor_sync(0xffffffffu, p[rr], off);
        }
        if (lane == 0) {
            float bc = b2[c];
            #pragma unroll
            for (int rr = 0; rr < 8; rr++)
                out[(row0 + rbase + rr) * CLS + c] = p[rr] + bc;
        }
    }
}

// ================= launch =================
extern "C" void kernel_launch(void* const* d_in, const int* in_sizes, int n_in,
                              void* d_out, int out_size) {
    const float* features = (const float*)d_in[0];
    const int*   src      = (const int*)d_in[1];
    const int*   dst      = (const int*)d_in[2];
    const float* W1       = (const float*)d_in[3];
    const float* b1       = (const float*)d_in[4];
    const float* W2       = (const float*)d_in[5];
    const float* b2       = (const float*)d_in[6];
    float* out = (float*)d_out;

    const int edge4Blocks = N_EDGES / 4 / 256;      // 625
    const int warpBlocks  = N_NODES * 32 / 256;     // 5000
    const int sortBlocks  = N_NODES / 8;            // 5000
    const int mlpBlocks   = N_NODES / 64;           // 625

    static int init_done = 0;
    if (!init_done) {
        cudaFuncSetAttribute(k_mlp, cudaFuncAttributeMaxDynamicSharedMemorySize,
                             MLP_SMEM);
        init_done = 1;
    }

    void* degPtr = nullptr;
    void* partPtr = nullptr;
    cudaGetSymbolAddress(&degPtr, g_deg);
    cudaGetSymbolAddress(&partPtr, g_part);
    cudaMemsetAsync(degPtr, 0, N_NODES * sizeof(int));
    cudaMemsetAsync(partPtr, 0xFF, NBLK * sizeof(int));   // -1 sentinels

    k_prepW<<<128, 256>>>(W1);
    k_deg4<<<edge4Blocks, 256>>>((const int4*)dst);
    k_scan<<<NBLK, 256>>>();
    k_prescale<<<warpBlocks, 256>>>((const float4*)features);
    k_fill4<<<edge4Blocks, 256>>>((const int4*)src, (const int4*)dst);
    k_sort<<<sortBlocks, 256>>>();

    k_gather1<<<warpBlocks, 256>>>();
    k_gather2<<<warpBlocks, 256>>>();
    k_mlp<<<mlpBlocks, 256, MLP_SMEM>>>(b1, W2, b2, out);
}

// round 11
// speedup vs baseline: 1.2987x; 1.0506x over previous
#include <cuda_runtime.h>
#include <cuda_fp16.h>
#include <cstdint>

#define N_NODES 40000
#define N_EDGES 640000
#define IN_F    128
#define HID     256
#define CLS     40
#define ROW4    (IN_F/4)
#define ROWH    32
#define NBLK    157

typedef unsigned long long ull;

// packed f32x2 helpers
#define FMA2(d, a, b)    asm("fma.rn.f32x2 %0, %1, %2, %3;" : "=l"(d) : "l"(a), "l"(b), "l"(d))
#define UNPACK2(lo, hi, s) asm("mov.b64 {%0, %1}, %2;" : "=f"(lo), "=f"(hi) : "l"(s))

__device__ __forceinline__ uint2 pack4h(float4 a) {
    __half2 lo = __floats2half2_rn(a.x, a.y);
    __half2 hi = __floats2half2_rn(a.z, a.w);
    uint2 r;
    r.x = *reinterpret_cast<unsigned*>(&lo);
    r.y = *reinterpret_cast<unsigned*>(&hi);
    return r;
}
__device__ __forceinline__ float4 unpack4h(uint2 v) {
    __half2 lo = *reinterpret_cast<__half2*>(&v.x);
    __half2 hi = *reinterpret_cast<__half2*>(&v.y);
    float2 a = __half22float2(lo);
    float2 b = __half22float2(hi);
    return make_float4(a.x, a.y, b.x, b.y);
}

// ---- scratch ----
__device__ int    g_deg[N_NODES];
__device__ int    g_rowptr[N_NODES + 1];
__device__ int    g_cursor[N_NODES];
__device__ int    g_part[NBLK];             // lookback partials (init -1 by k_deg4)
__device__ int    g_csr[N_EDGES];
__device__ float  g_norm[N_NODES];
__device__ uint2  g_featH[N_NODES * ROWH];  // feat*norm fp16; REUSED as hop2 out
__device__ uint2  g_bufH[N_NODES * ROWH];   // hop1 out, fp16
__device__ __half g_W1h[HID * IN_F];        // W1^T fp16: [n][k]

// ================= slot 2: degree + W1 prep + g_part sentinels =================
__global__ __launch_bounds__(256)
void k_deg4(const int4* __restrict__ dst4, const float* __restrict__ W1) {
    int e = blockIdx.x * blockDim.x + threadIdx.x;   // grid 625*256 -> 640000 edges
    int4 d = dst4[e];
    atomicAdd(&g_deg[d.x], 1);
    atomicAdd(&g_deg[d.y], 1);
    atomicAdd(&g_deg[d.z], 1);
    atomicAdd(&g_deg[d.w], 1);
    if (blockIdx.x < 128) {                          // W1^T fp16 prep (32768 elems)
        int i = blockIdx.x * 256 + threadIdx.x;
        int k = i >> 8, n = i & 255;
        g_W1h[n * IN_F + k] = __float2half(W1[i]);
    }
    if (blockIdx.x == 624 && threadIdx.x < NBLK)     // lookback sentinels for k_scan
        g_part[threadIdx.x] = -1;
}

// ================= slot 3: scan (lookback) + cursor + norm + prescale =================
__global__ __launch_bounds__(256)
void k_scan(const float4* __restrict__ feat4) {
    __shared__ int   sm[256];
    __shared__ float smN[256];
    const int t = threadIdx.x;
    const int b = blockIdx.x;
    const int i = b * 256 + t;
    int v = (i < N_NODES) ? g_deg[i] : 0;

    sm[t] = v;
    __syncthreads();
    int acc = v;
    for (int o = 1; o < 256; o <<= 1) {
        int u = (t >= o) ? sm[t - o] : 0;
        __syncthreads();
        acc += u;
        sm[t] = acc;
        __syncthreads();
    }
    int S = sm[255];

    if (t == 0) atomicExch(&g_part[b], S);

    int part = 0;
    if (t < b) {
        int p;
        do { p = atomicAdd(&g_part[t], 0); } while (p < 0);
        part = p;
    }
    __syncthreads();
    sm[t] = part;
    __syncthreads();
    for (int o = 128; o > 0; o >>= 1) {
        if (t < o) sm[t] += sm[t + o];
        __syncthreads();
    }
    int off = sm[0];

    float nrm = rsqrtf(fmaxf((float)v, 1.0f));
    smN[t] = nrm;
    if (i < N_NODES) {
        int rp = acc - v + off;
        g_rowptr[i] = rp;
        g_cursor[i] = rp;
        g_norm[i] = nrm;
    }
    if (b == NBLK - 1 && t == 0) g_rowptr[N_NODES] = off + S;
    __syncthreads();

    // fused prescale: featH[node][c] = fp16(feat * norm), coalesced within block
    const int nodeBase = b * 256;
    for (int idx = t; idx < 256 * ROWH; idx += 256) {
        int node = nodeBase + (idx >> 5);
        if (node < N_NODES) {
            float n = smN[idx >> 5];
            float4 x = feat4[node * ROWH + (idx & 31)];
            x.x *= n; x.y *= n; x.z *= n; x.w *= n;
            g_featH[node * ROWH + (idx & 31)] = pack4h(x);
        }
    }
}

// ================= slot 4: CSR fill =================
__global__ __launch_bounds__(256)
void k_fill4(const int4* __restrict__ src4, const int4* __restrict__ dst4) {
    int e = blockIdx.x * blockDim.x + threadIdx.x;
    int4 s = src4[e];
    int4 d = dst4[e];
    g_csr[atomicAdd(&g_cursor[d.x], 1)] = s.x;
    g_csr[atomicAdd(&g_cursor[d.y], 1)] = s.y;
    g_csr[atomicAdd(&g_cursor[d.z], 1)] = s.z;
    g_csr[atomicAdd(&g_cursor[d.w], 1)] = s.w;
}

// ================= slot 5: per-node sort (deterministic order) =================
__global__ __launch_bounds__(256)
void k_sort() {
    __shared__ int scratch[8][512];
    const int wi   = threadIdx.x >> 5;
    const int lane = threadIdx.x & 31;
    const int n = blockIdx.x * 8 + wi;
    int b = g_rowptr[n], e = g_rowptr[n + 1];
    int d = e - b;
    if (d <= 1) return;
    if (d <= 32) {
        int v = (lane < d) ? g_csr[b + lane] : 0x7fffffff;
        #pragma unroll
        for (int k = 2; k <= 32; k <<= 1) {
            #pragma unroll
            for (int j = k >> 1; j > 0; j >>= 1) {
                int pv = __shfl_xor_sync(0xffffffffu, v, j);
                bool dir   = ((lane & k) == 0);
                bool lower = ((lane & j) == 0);
                v = ((lower == dir) ? min(v, pv) : max(v, pv));
            }
        }
        if (lane < d) g_csr[b + lane] = v;
    } else if (d <= 512) {
        // warp-parallel bitonic over padded pow2 (kills the serial insertion tail)
        int* s = scratch[wi];
        int n2 = 64; while (n2 < d) n2 <<= 1;
        for (int i = lane; i < n2; i += 32) s[i] = (i < d) ? g_csr[b + i] : 0x7fffffff;
        __syncwarp();
        for (int k = 2; k <= n2; k <<= 1) {
            for (int j = k >> 1; j > 0; j >>= 1) {
                for (int i = lane; i < n2; i += 32) {
                    int p = i ^ j;
                    if (p > i) {
                        int a = s[i], c = s[p];
                        bool dir = ((i & k) == 0);
                        if ((a > c) == dir) { s[i] = c; s[p] = a; }
                    }
                }
                __syncwarp();
            }
        }
        for (int i = lane; i < d; i += 32) g_csr[b + i] = s[i];
    } else {
        if (lane == 0) {   // unreachable safety net
            for (int i = b + 1; i < e; i++) {
                int v = g_csr[i], j = i - 1;
                while (j >= b && g_csr[j] > v) { g_csr[j + 1] = g_csr[j]; j--; }
                g_csr[j + 1] = v;
            }
        }
    }
}

// ================= slot 6 (PROFILED): hop 1 gather =================
__global__ __launch_bounds__(256)
void k_gather1() {
    int gt = blockIdx.x * blockDim.x + threadIdx.x;
    int w = gt >> 5, lane = gt & 31;
    int beg = g_rowptr[w], end = g_rowptr[w + 1];
    float4 acc = make_float4(0.f, 0.f, 0.f, 0.f);
    for (int base = beg; base < end; base += 32) {
        int cnt = min(32, end - base);
        int idx = base + lane;
        int s_l = (idx < end) ? g_csr[idx] : 0;
        int k = 0;
        for (; k + 8 <= cnt; k += 8) {
            int s[8];
            #pragma unroll
            for (int i = 0; i < 8; i++) s[i] = __shfl_sync(0xffffffffu, s_l, k + i);
            uint2 h[8];
            #pragma unroll
            for (int i = 0; i < 8; i++) h[i] = g_featH[s[i] * ROWH + lane];
            #pragma unroll
            for (int i = 0; i < 8; i++) {
                float4 v = unpack4h(h[i]);
                acc.x += v.x; acc.y += v.y; acc.z += v.z; acc.w += v.w;
            }
        }
        for (; k < cnt; k++) {
            int s = __shfl_sync(0xffffffffu, s_l, k);
            float4 v = unpack4h(g_featH[s * ROWH + lane]);
            acc.x += v.x; acc.y += v.y; acc.z += v.z; acc.w += v.w;
        }
    }
    float nn = g_norm[w];
    float sc = nn * nn;
    acc.x *= sc; acc.y *= sc; acc.z *= sc; acc.w *= sc;
    g_bufH[w * ROWH + lane] = pack4h(acc);
}

// ================= slot 7: hop 2 gather (writes into dead g_featH) =================
__global__ __launch_bounds__(256)
void k_gather2() {
    int gt = blockIdx.x * blockDim.x + threadIdx.x;
    int w = gt >> 5, lane = gt & 31;
    int beg = g_rowptr[w], end = g_rowptr[w + 1];
    float4 acc = make_float4(0.f, 0.f, 0.f, 0.f);
    for (int base = beg; base < end; base += 32) {
        int cnt = min(32, end - base);
        int idx = base + lane;
        int s_l = (idx < end) ? g_csr[idx] : 0;
        int k = 0;
        for (; k + 8 <= cnt; k += 8) {
            int s[8];
            #pragma unroll
            for (int i = 0; i < 8; i++) s[i] = __shfl_sync(0xffffffffu, s_l, k + i);
            uint2 h[8];
            #pragma unroll
            for (int i = 0; i < 8; i++) h[i] = g_bufH[s[i] * ROWH + lane];
            #pragma unroll
            for (int i = 0; i < 8; i++) {
                float4 v = unpack4h(h[i]);
                acc.x += v.x; acc.y += v.y; acc.z += v.z; acc.w += v.w;
            }
        }
        for (; k < cnt; k++) {
            int s = __shfl_sync(0xffffffffu, s_l, k);
            float4 v = unpack4h(g_bufH[s * ROWH + lane]);
            acc.x += v.x; acc.y += v.y; acc.z += v.z; acc.w += v.w;
        }
    }
    float nn = g_norm[w];
    acc.x *= nn; acc.y *= nn; acc.z *= nn; acc.w *= nn;
    g_featH[w * ROWH + lane] = pack4h(acc);
}

// ================= slot 8: MLP via mma.sync (HMMA) =================
#define HPAD 68
#define ZSTR 264
#define MLP_SMEM 129024
__global__ __launch_bounds__(256)
void k_mlp(const float* __restrict__ b1, const float* __restrict__ W2,
           const float* __restrict__ b2, float* __restrict__ out) {
    extern __shared__ __align__(16) char dyn[];
    unsigned* smHA  = reinterpret_cast<unsigned*>(dyn);                // fp16 [64][136]
    unsigned* smW1  = reinterpret_cast<unsigned*>(dyn + 17408);        // fp16 [256][136]
    float*    smZ   = reinterpret_cast<float*>(dyn + 17408);           // fp32 [64][264]
    float*    smW2  = reinterpret_cast<float*>(dyn + 87040);           // fp32 [40][256]
    float*    smB1  = reinterpret_cast<float*>(dyn + 128000);          // fp32 [256]

    const int t    = threadIdx.x;
    const int wid  = t >> 5;
    const int lane = t & 31;
    const int row0 = blockIdx.x * 64;

    const unsigned* srcH = reinterpret_cast<const unsigned*>(g_featH) + row0 * 64;
    #pragma unroll
    for (int it = 0; it < 16; it++) {
        int idx = it * 256 + t;
        int r = idx >> 6, c = idx & 63;
        smHA[r * HPAD + c] = srcH[idx];
    }
    {
        const uint4* srcW = reinterpret_cast<const uint4*>(g_W1h);
        uint4* dstW = reinterpret_cast<uint4*>(smW1);
        #pragma unroll
        for (int it = 0; it < 16; it++) {
            int idx = it * 256 + t;
            int r = idx >> 4, q = idx & 15;
            dstW[r * 17 + q] = srcW[idx];
        }
    }
    smB1[t] = b1[t];
    __syncthreads();

    const int mrow0 = (wid & 3) * 16;
    const int ncol0 = (wid >> 2) * 128;
    const int g  = lane >> 2;
    const int ct = lane & 3;

    float acc[16][4];
    #pragma unroll
    for (int nt = 0; nt < 16; nt++)
        #pragma unroll
        for (int q = 0; q < 4; q++) acc[nt][q] = 0.f;

    #pragma unroll
    for (int kt = 0; kt < 8; kt++) {
        const int kw = kt * 8 + ct;
        unsigned a0 = smHA[(mrow0 + g) * HPAD + kw];
        unsigned a1 = smHA[(mrow0 + g + 8) * HPAD + kw];
        unsigned a2 = smHA[(mrow0 + g) * HPAD + kw + 4];
        unsigned a3 = smHA[(mrow0 + g + 8) * HPAD + kw + 4];
        #pragma unroll
        for (int nt = 0; nt < 16; nt++) {
            const int n = ncol0 + nt * 8 + g;
            unsigned b0 = smW1[n * HPAD + kw];
            unsigned b1r = smW1[n * HPAD + kw + 4];
            asm volatile(
                "mma.sync.aligned.m16n8k16.row.col.f32.f16.f16.f32 "
                "{%0,%1,%2,%3}, {%4,%5,%6,%7}, {%8,%9}, {%0,%1,%2,%3};"
                : "+f"(acc[nt][0]), "+f"(acc[nt][1]), "+f"(acc[nt][2]), "+f"(acc[nt][3])
                : "r"(a0), "r"(a1), "r"(a2), "r"(a3), "r"(b0), "r"(b1r));
        }
    }

    for (int i = t; i < CLS * HID; i += 256) {
        int c = i >> 8, k = i & 255;
        smW2[c * HID + k] = W2[k * CLS + c];
    }

    __syncthreads();
    #pragma unroll
    for (int nt = 0; nt < 16; nt++) {
        const int col = ncol0 + nt * 8 + ct * 2;
        float bi0 = smB1[col], bi1 = smB1[col + 1];
        float2 z0, z1;
        z0.x = fmaxf(acc[nt][0] + bi0, 0.f);
        z0.y = fmaxf(acc[nt][1] + bi1, 0.f);
        z1.x = fmaxf(acc[nt][2] + bi0, 0.f);
        z1.y = fmaxf(acc[nt][3] + bi1, 0.f);
        *reinterpret_cast<float2*>(smZ + (mrow0 + g) * ZSTR + col)     = z0;
        *reinterpret_cast<float2*>(smZ + (mrow0 + g + 8) * ZSTR + col) = z1;
    }
    __syncthreads();

    const int rbase = wid * 8;
    ull zp[8][4];
    #pragma unroll
    for (int rr = 0; rr < 8; rr++) {
        const ulonglong2* zr =
            reinterpret_cast<const ulonglong2*>(smZ + (rbase + rr) * ZSTR + lane * 8);
        ulonglong2 a = zr[0], b = zr[1];
        zp[rr][0] = a.x; zp[rr][1] = a.y; zp[rr][2] = b.x; zp[rr][3] = b.y;
    }
    #pragma unroll 1
    for (int c = 0; c < CLS; c++) {
        const ulonglong2* wp =
            reinterpret_cast<const ulonglong2*>(smW2 + c * HID + lane * 8);
        ulonglong2 wA = wp[0], wB = wp[1];
        float p[8];
        #pragma unroll
        for (int rr = 0; rr < 8; rr++) {
            ull s2 = 0ull;
            FMA2(s2, zp[rr][0], wA.x);
            FMA2(s2, zp[rr][1], wA.y);
            FMA2(s2, zp[rr][2], wB.x);
            FMA2(s2, zp[rr][3], wB.y);
            float lo, hi;
            UNPACK2(lo, hi, s2);
            p[rr] = lo + hi;
        }
        #pragma unroll
        for (int off = 16; off > 0; off >>= 1) {
            #pragma unroll
            for (int rr = 0; rr < 8; rr++)
                p[rr] += __shfl_xor_sync(0xffffffffu, p[rr], off);
        }
        if (lane == 0) {
            float bc = b2[c];
            #pragma unroll
            for (int rr = 0; rr < 8; rr++)
                out[(row0 + rbase + rr) * CLS + c] = p[rr] + bc;
        }
    }
}

// ================= launch =================
extern "C" void kernel_launch(void* const* d_in, const int* in_sizes, int n_in,
                              void* d_out, int out_size) {
    const float* features = (const float*)d_in[0];
    const int*   src      = (const int*)d_in[1];
    const int*   dst      = (const int*)d_in[2];
    const float* W1       = (const float*)d_in[3];
    const float* b1       = (const float*)d_in[4];
    const float* W2       = (const float*)d_in[5];
    const float* b2       = (const float*)d_in[6];
    float* out = (float*)d_out;

    const int edge4Blocks = N_EDGES / 4 / 256;      // 625
    const int warpBlocks  = N_NODES * 32 / 256;     // 5000
    const int sortBlocks  = N_NODES / 8;            // 5000
    const int mlpBlocks   = N_NODES / 64;           // 625

    static int init_done = 0;
    if (!init_done) {
        cudaFuncSetAttribute(k_mlp, cudaFuncAttributeMaxDynamicSharedMemorySize,
                             MLP_SMEM);
        init_done = 1;
    }

    void* degPtr = nullptr;
    cudaGetSymbolAddress(&degPtr, g_deg);
    cudaMemsetAsync(degPtr, 0, N_NODES * sizeof(int));          // slot 1

    k_deg4<<<edge4Blocks, 256>>>((const int4*)dst, W1);         // slot 2
    k_scan<<<NBLK, 256>>>((const float4*)features);             // slot 3
    k_fill4<<<edge4Blocks, 256>>>((const int4*)src, (const int4*)dst);  // slot 4
    k_sort<<<sortBlocks, 256>>>();                              // slot 5
    k_gather1<<<warpBlocks, 256>>>();                           // slot 6 (profiled)
    k_gather2<<<warpBlocks, 256>>>();                           // slot 7
    k_mlp<<<mlpBlocks, 256, MLP_SMEM>>>(b1, W2, b2, out);       // slot 8
}